// round 4
// baseline (speedup 1.0000x reference)
#include <cuda_runtime.h>

#define B_   8
#define C_   64
#define NPTS 2048
#define MFRQ 4032
#define F1   2048
#define KC   32

// -------- scratch (device globals; no allocation in kernel_launch) ----------
__device__ __align__(16) float2 g_Xft[B_ * C_ * F1];   // forward result {re, im},  [b][c][f]
__device__ __align__(16) float2 g_xf [B_ * C_ * MFRQ]; // Hermitian-expanded {re, -im}, [b][c][f]
__device__ float2 g_phi[2 * B_ * 1024];                // [mod][b][x(32)][y(32)]

// -------- packed f32x2 helpers ----------------------------------------------
__device__ __forceinline__ unsigned long long pack2(float lo, float hi) {
    unsigned long long r;
    asm("mov.b64 %0, {%1, %2};" : "=l"(r) : "f"(lo), "f"(hi));
    return r;
}
__device__ __forceinline__ float2 unpack2(unsigned long long v) {
    float2 r;
    asm("mov.b64 {%0, %1}, %2;" : "=f"(r.x), "=f"(r.y) : "l"(v));
    return r;
}
__device__ __forceinline__ void fma2(unsigned long long &d,
                                     unsigned long long a,
                                     unsigned long long b) {
    asm("fma.rn.f32x2 %0, %1, %2, %0;" : "+l"(d) : "l"(a), "l"(b));
}

// ============================================================================
// Kernel 1: phi[b,x,y] = sum_e mod[x,y,e] * emb[b,e]   (complex mod, real emb)
// grid 2048 = (mod 2) x (x 32) x (y 32); 256 threads; warp w = batch b.
// ============================================================================
__global__ __launch_bounds__(256) void k_phi(
    const float* __restrict__ emb,
    const float* __restrict__ m1re, const float* __restrict__ m1im,
    const float* __restrict__ m2re, const float* __restrict__ m2im)
{
    __shared__ float s_re[256];
    __shared__ float s_im[256];
    const int bid = blockIdx.x;
    const int mod = bid >> 10;
    const int xy  = bid & 1023;
    const int tid = threadIdx.x;

    const float* mre = (mod ? m2re : m1re) + (size_t)xy * 256;
    const float* mim = (mod ? m2im : m1im) + (size_t)xy * 256;
    s_re[tid] = mre[tid];
    s_im[tid] = mim[tid];
    __syncthreads();

    const int w = tid >> 5;   // batch
    const int l = tid & 31;
    float pr = 0.f, pi = 0.f;
#pragma unroll
    for (int j = 0; j < 8; j++) {
        int e = l + j * 32;
        float ee = emb[w * 256 + e];
        pr += s_re[e] * ee;
        pi += s_im[e] * ee;
    }
#pragma unroll
    for (int off = 16; off > 0; off >>= 1) {
        pr += __shfl_down_sync(0xffffffffu, pr, off);
        pi += __shfl_down_sync(0xffffffffu, pi, off);
    }
    if (l == 0) g_phi[mod * (B_ * 1024) + w * 1024 + xy] = make_float2(pr, pi);
}

// ============================================================================
// Kernel 2: forward NUFT on the 2048 needed modes.
// Xft[b,c,f] = sum_n Vf[row(f), n] * x[b,c,n],  row(f) = (f>>5)*63 + (f&31)
// Block tile: 128 f x 64 c, 128 threads, per-thread 8x8 packed (re,im) accums.
// grid (16 f-tiles, 8 batches).
// ============================================================================
__global__ __launch_bounds__(128) void k_forward(
    const float* __restrict__ x,
    const float* __restrict__ vfre,
    const float* __restrict__ vfim)
{
    __shared__ float2 As[KC][128];  // [k][f] {vf_re, vf_im}
    __shared__ float  Xs[KC][C_];   // [k][c]

    const int b     = blockIdx.y;
    const int ftile = blockIdx.x;
    const int tid   = threadIdx.x;
    const int tx    = tid & 7;      // c-group (8 c's)
    const int ty    = tid >> 3;     // f-group (8 f's)

    unsigned long long acc[8][8];
#pragma unroll
    for (int i = 0; i < 8; i++)
#pragma unroll
        for (int j = 0; j < 8; j++) acc[i][j] = 0ull;

    const float* xb = x + (size_t)b * C_ * NPTS;

    for (int kb = 0; kb < NPTS; kb += KC) {
        // A: 128 f x 32 k  (re & im interleaved into smem)
#pragma unroll
        for (int p = 0; p < 8; p++) {
            int f  = p * 16 + (tid >> 3);
            int k4 = (tid & 7) * 4;
            int fg = ftile * 128 + f;
            int row = (fg >> 5) * 63 + (fg & 31);
            float4 r4 = *reinterpret_cast<const float4*>(vfre + (size_t)row * NPTS + kb + k4);
            float4 i4 = *reinterpret_cast<const float4*>(vfim + (size_t)row * NPTS + kb + k4);
            As[k4 + 0][f] = make_float2(r4.x, i4.x);
            As[k4 + 1][f] = make_float2(r4.y, i4.y);
            As[k4 + 2][f] = make_float2(r4.z, i4.z);
            As[k4 + 3][f] = make_float2(r4.w, i4.w);
        }
        // X: 64 c x 32 k
#pragma unroll
        for (int p = 0; p < 4; p++) {
            int c  = p * 16 + (tid >> 3);
            int k4 = (tid & 7) * 4;
            float4 v = *reinterpret_cast<const float4*>(xb + (size_t)c * NPTS + kb + k4);
            Xs[k4 + 0][c] = v.x;
            Xs[k4 + 1][c] = v.y;
            Xs[k4 + 2][c] = v.z;
            Xs[k4 + 3][c] = v.w;
        }
        __syncthreads();

#pragma unroll 2
        for (int k = 0; k < KC; k++) {
            unsigned long long a[8];
            const ulonglong2* ap = reinterpret_cast<const ulonglong2*>(&As[k][ty * 8]);
#pragma unroll
            for (int i = 0; i < 4; i++) { ulonglong2 t = ap[i]; a[2*i] = t.x; a[2*i+1] = t.y; }
            const float4* xp = reinterpret_cast<const float4*>(&Xs[k][tx * 8]);
            float4 x0 = xp[0], x1 = xp[1];
            unsigned long long xv[8];
            xv[0] = pack2(x0.x, x0.x); xv[1] = pack2(x0.y, x0.y);
            xv[2] = pack2(x0.z, x0.z); xv[3] = pack2(x0.w, x0.w);
            xv[4] = pack2(x1.x, x1.x); xv[5] = pack2(x1.y, x1.y);
            xv[6] = pack2(x1.z, x1.z); xv[7] = pack2(x1.w, x1.w);
#pragma unroll
            for (int fi = 0; fi < 8; fi++)
#pragma unroll
                for (int ci = 0; ci < 8; ci++)
                    fma2(acc[fi][ci], a[fi], xv[ci]);
        }
        __syncthreads();
    }

    const int f0 = ftile * 128 + ty * 8;
#pragma unroll
    for (int ci = 0; ci < 8; ci++) {
        int c = tx * 8 + ci;
        ulonglong2* dst = reinterpret_cast<ulonglong2*>(&g_Xft[((size_t)(b * C_ + c)) * F1 + f0]);
#pragma unroll
        for (int i = 0; i < 4; i++) {
            ulonglong2 t;
            t.x = acc[2 * i][ci];
            t.y = acc[2 * i + 1][ci];
            dst[i] = t;
        }
    }
}

// ============================================================================
// Kernel 3: channel mixing + phi modulation + Hermitian expansion.
// For mode (x,y): out[b,o] = phi_{sel}[b, x&31, y] * sum_i Xft[b,i,x*32+y]*w[i,o,x&31,y]
// Writes g_xf primary {re,-im} at fm=x*32+y, mirror {re,+im} at 4095-fm (fm>=64).
// grid 256 = (x 64) x (y-half 2) x (b-half 2); 512 threads.
// ============================================================================
__global__ __launch_bounds__(512) void k_mix(
    const float* __restrict__ w1re, const float* __restrict__ w1im,
    const float* __restrict__ w2re, const float* __restrict__ w2im)
{
    __shared__ float2 Xs[4][64][16];   // [b_local][i][y_local]

    const int bid = blockIdx.x;
    const int xm  = bid >> 2;
    const int yh  = (bid >> 1) & 1;
    const int bh  = bid & 1;
    const int tid = threadIdx.x;

    // cooperative load of Xft slice: 4 b x 64 i x 16 y (float2)
    {
        int row  = tid >> 1;        // 0..255
        int half = tid & 1;
        int br = row >> 6, ii = row & 63;
        const float2* src = g_Xft + ((size_t)((bh * 4 + br) * C_ + ii)) * F1
                            + xm * 32 + yh * 16 + half * 8;
#pragma unroll
        for (int j = 0; j < 4; j++) {
            float4 v = reinterpret_cast<const float4*>(src)[j];
            Xs[br][ii][half * 8 + j * 2]     = make_float2(v.x, v.y);
            Xs[br][ii][half * 8 + j * 2 + 1] = make_float2(v.z, v.w);
        }
    }
    __syncthreads();

    const int o   = tid >> 3;      // 0..63 output channel
    const int yq  = tid & 7;       // y pair index
    const int y   = yh * 16 + yq * 2;
    const int x32 = xm & 31;
    const float* wre = (xm < 32) ? w1re : w2re;
    const float* wim = (xm < 32) ? w1im : w2im;

    unsigned long long acc0[4] = {0ull, 0ull, 0ull, 0ull};  // packed (s_re, s_im)
    unsigned long long acc1[4] = {0ull, 0ull, 0ull, 0ull};

#pragma unroll 4
    for (int ii = 0; ii < 64; ii++) {
        size_t wrow = (size_t)(ii * 64 + o) * 1024 + x32 * 32 + y;
        float2 wr = *reinterpret_cast<const float2*>(wre + wrow);
        float2 wi = *reinterpret_cast<const float2*>(wim + wrow);
        unsigned long long w0a = pack2(wr.x, wi.x);
        unsigned long long w0b = pack2(-wi.x, wr.x);
        unsigned long long w1a = pack2(wr.y, wi.y);
        unsigned long long w1b = pack2(-wi.y, wr.y);
#pragma unroll
        for (int br = 0; br < 4; br++) {
            float2 xv0 = Xs[br][ii][yq * 2];
            float2 xv1 = Xs[br][ii][yq * 2 + 1];
            fma2(acc0[br], pack2(xv0.x, xv0.x), w0a);
            fma2(acc0[br], pack2(xv0.y, xv0.y), w0b);
            fma2(acc1[br], pack2(xv1.x, xv1.x), w1a);
            fma2(acc1[br], pack2(xv1.y, xv1.y), w1b);
        }
    }

    const int sel = (xm < 32) ? 0 : 1;
#pragma unroll
    for (int br = 0; br < 4; br++) {
        int bb = bh * 4 + br;
#pragma unroll
        for (int pp = 0; pp < 2; pp++) {
            int yy = y + pp;
            float2 s = unpack2(pp ? acc1[br] : acc0[br]);
            float2 p = g_phi[sel * (B_ * 1024) + bb * 1024 + x32 * 32 + yy];
            float vr = p.x * s.x - p.y * s.y;
            float vi = p.x * s.y + p.y * s.x;
            int fm = xm * 32 + yy;
            g_xf[((size_t)(bb * C_ + o)) * MFRQ + fm] = make_float2(vr, -vi);
            if (fm >= 64)
                g_xf[((size_t)(bb * C_ + (63 - o))) * MFRQ + (4095 - fm)] = make_float2(vr, vi);
        }
    }
}

// ============================================================================
// Kernel 4: inverse NUFT (real part), K = 4032.
// out[b,c,n] = (2/N) * sum_f (Vi_re[n,f]*xf_re + Vi_im[n,f]*(-xf_im))
// Packed accumulation; final horizontal add. Block tile 128 n x 64 c, 128 thr.
// ============================================================================
__global__ __launch_bounds__(128) void k_inverse(
    const float* __restrict__ vire,
    const float* __restrict__ viim,
    float* __restrict__ out)
{
    __shared__ float2 As[KC][128];  // [k][n] {vi_re, vi_im}
    __shared__ float2 Xs[KC][C_];   // [k][c] {xf_re, -xf_im}

    const int b     = blockIdx.y;
    const int ntile = blockIdx.x;
    const int tid   = threadIdx.x;
    const int tx    = tid & 7;
    const int ty    = tid >> 3;

    unsigned long long acc[8][8];
#pragma unroll
    for (int i = 0; i < 8; i++)
#pragma unroll
        for (int j = 0; j < 8; j++) acc[i][j] = 0ull;

    for (int kb = 0; kb < MFRQ; kb += KC) {
        // A: 128 n x 32 k (re & im interleaved)
#pragma unroll
        for (int p = 0; p < 8; p++) {
            int n  = p * 16 + (tid >> 3);
            int k4 = (tid & 7) * 4;
            int row = ntile * 128 + n;
            float4 r4 = *reinterpret_cast<const float4*>(vire + (size_t)row * MFRQ + kb + k4);
            float4 i4 = *reinterpret_cast<const float4*>(viim + (size_t)row * MFRQ + kb + k4);
            As[k4 + 0][n] = make_float2(r4.x, i4.x);
            As[k4 + 1][n] = make_float2(r4.y, i4.y);
            As[k4 + 2][n] = make_float2(r4.z, i4.z);
            As[k4 + 3][n] = make_float2(r4.w, i4.w);
        }
        // X: 64 c x 32 k (already interleaved in g_xf)
#pragma unroll
        for (int p = 0; p < 8; p++) {
            int c  = p * 8 + (tid >> 4);
            int k2 = (tid & 15) * 2;
            const float2* src = g_xf + ((size_t)(b * C_ + c)) * MFRQ + kb + k2;
            float4 v = *reinterpret_cast<const float4*>(src);
            Xs[k2][c]     = make_float2(v.x, v.y);
            Xs[k2 + 1][c] = make_float2(v.z, v.w);
        }
        __syncthreads();

#pragma unroll 2
        for (int k = 0; k < KC; k++) {
            unsigned long long a[8], xv[8];
            const ulonglong2* ap = reinterpret_cast<const ulonglong2*>(&As[k][ty * 8]);
#pragma unroll
            for (int i = 0; i < 4; i++) { ulonglong2 t = ap[i]; a[2*i] = t.x; a[2*i+1] = t.y; }
            const ulonglong2* xp = reinterpret_cast<const ulonglong2*>(&Xs[k][tx * 8]);
#pragma unroll
            for (int i = 0; i < 4; i++) { ulonglong2 t = xp[i]; xv[2*i] = t.x; xv[2*i+1] = t.y; }
#pragma unroll
            for (int fi = 0; fi < 8; fi++)
#pragma unroll
                for (int ci = 0; ci < 8; ci++)
                    fma2(acc[fi][ci], a[fi], xv[ci]);
        }
        __syncthreads();
    }

    const float sc = 2.0f / (float)NPTS;
    const int n0 = ntile * 128 + ty * 8;
#pragma unroll
    for (int ci = 0; ci < 8; ci++) {
        int c = tx * 8 + ci;
        float r[8];
#pragma unroll
        for (int fi = 0; fi < 8; fi++) {
            float2 s = unpack2(acc[fi][ci]);
            r[fi] = (s.x + s.y) * sc;
        }
        float4* dst = reinterpret_cast<float4*>(out + ((size_t)(b * C_ + c)) * NPTS + n0);
        dst[0] = make_float4(r[0], r[1], r[2], r[3]);
        dst[1] = make_float4(r[4], r[5], r[6], r[7]);
    }
}

// ============================================================================
extern "C" void kernel_launch(void* const* d_in, const int* in_sizes, int n_in,
                              void* d_out, int out_size)
{
    const float* x     = (const float*)d_in[0];
    const float* emb   = (const float*)d_in[1];
    const float* vf_re = (const float*)d_in[2];
    const float* vf_im = (const float*)d_in[3];
    const float* vi_re = (const float*)d_in[4];
    const float* vi_im = (const float*)d_in[5];
    const float* w1_re = (const float*)d_in[6];
    const float* w1_im = (const float*)d_in[7];
    const float* w2_re = (const float*)d_in[8];
    const float* w2_im = (const float*)d_in[9];
    const float* m1_re = (const float*)d_in[10];
    const float* m1_im = (const float*)d_in[11];
    const float* m2_re = (const float*)d_in[12];
    const float* m2_im = (const float*)d_in[13];
    float* out = (float*)d_out;

    k_phi<<<2048, 256>>>(emb, m1_re, m1_im, m2_re, m2_im);
    k_forward<<<dim3(16, 8), 128>>>(x, vf_re, vf_im);
    k_mix<<<256, 512>>>(w1_re, w1_im, w2_re, w2_im);
    k_inverse<<<dim3(16, 8), 128>>>(vi_re, vi_im, out);
}

// round 5
// speedup vs baseline: 1.4208x; 1.4208x over previous
#include <cuda_runtime.h>

#define B_   8
#define C_   64
#define NPTS 2048
#define MFRQ 4032
#define F1   2048
#define KC   16

// -------- scratch (device globals; no allocation in kernel_launch) ----------
__device__ __align__(16) float2 g_Xft[B_ * C_ * F1];   // forward result {re, im},  [b][c][f]
__device__ __align__(16) float2 g_xf [B_ * C_ * MFRQ]; // Hermitian-expanded {re, -im}, [b][c][f]
__device__ float2 g_phi[2 * B_ * 1024];                // [mod][b][x(32)][y(32)]

// -------- packed f32x2 helpers ----------------------------------------------
__device__ __forceinline__ unsigned long long pack2(float lo, float hi) {
    unsigned long long r;
    asm("mov.b64 %0, {%1, %2};" : "=l"(r) : "f"(lo), "f"(hi));
    return r;
}
__device__ __forceinline__ float2 unpack2(unsigned long long v) {
    float2 r;
    asm("mov.b64 {%0, %1}, %2;" : "=f"(r.x), "=f"(r.y) : "l"(v));
    return r;
}
__device__ __forceinline__ void fma2(unsigned long long &d,
                                     unsigned long long a,
                                     unsigned long long b) {
    asm("fma.rn.f32x2 %0, %1, %2, %0;" : "+l"(d) : "l"(a), "l"(b));
}
__device__ __forceinline__ void add2(unsigned long long &d, unsigned long long a) {
    asm("add.rn.f32x2 %0, %0, %1;" : "+l"(d) : "l"(a));
}
// warpgroup-scoped barrier (ids 1 and 2), 128 threads each
#define WG_BAR(id) asm volatile("bar.sync %0, 128;" :: "r"(id) : "memory")

// ============================================================================
// Kernel 1: phi[b,x,y] = sum_e mod[x,y,e] * emb[b,e]
// ============================================================================
__global__ __launch_bounds__(256) void k_phi(
    const float* __restrict__ emb,
    const float* __restrict__ m1re, const float* __restrict__ m1im,
    const float* __restrict__ m2re, const float* __restrict__ m2im)
{
    __shared__ float s_re[256];
    __shared__ float s_im[256];
    const int bid = blockIdx.x;
    const int mod = bid >> 10;
    const int xy  = bid & 1023;
    const int tid = threadIdx.x;

    const float* mre = (mod ? m2re : m1re) + (size_t)xy * 256;
    const float* mim = (mod ? m2im : m1im) + (size_t)xy * 256;
    s_re[tid] = mre[tid];
    s_im[tid] = mim[tid];
    __syncthreads();

    const int w = tid >> 5;
    const int l = tid & 31;
    float pr = 0.f, pi = 0.f;
#pragma unroll
    for (int j = 0; j < 8; j++) {
        int e = l + j * 32;
        float ee = emb[w * 256 + e];
        pr += s_re[e] * ee;
        pi += s_im[e] * ee;
    }
#pragma unroll
    for (int off = 16; off > 0; off >>= 1) {
        pr += __shfl_down_sync(0xffffffffu, pr, off);
        pi += __shfl_down_sync(0xffffffffu, pi, off);
    }
    if (l == 0) g_phi[mod * (B_ * 1024) + w * 1024 + xy] = make_float2(pr, pi);
}

// ============================================================================
// Kernel 2: forward NUFT, in-block split-K (2 warpgroups x K/2 each).
// Xft[b,c,f] = sum_n Vf[row(f), n] * x[b,c,n],  row(f) = (f>>5)*63 + (f&31)
// Tile 128f x 64c; 256 threads; per-thread 8x8 packed {re,im} accums.
// ============================================================================
__global__ __launch_bounds__(256, 1) void k_forward(
    const float* __restrict__ x,
    const float* __restrict__ vfre,
    const float* __restrict__ vfim)
{
    __shared__ float2 As[2][KC][128];  // per-wg: [k][f] {vf_re, vf_im}  (32 KB)
    __shared__ float  Xs[2][KC][C_];   // per-wg: [k][c]                 (8 KB)

    const int b     = blockIdx.y;
    const int ftile = blockIdx.x;
    const int tid   = threadIdx.x;
    const int wg    = tid >> 7;       // 0/1 warpgroup
    const int wtid  = tid & 127;
    const int tx    = wtid & 7;       // c-group
    const int ty    = wtid >> 3;      // f-group

    unsigned long long acc[8][8];
#pragma unroll
    for (int i = 0; i < 8; i++)
#pragma unroll
        for (int j = 0; j < 8; j++) acc[i][j] = 0ull;

    const int kbase = wg * (NPTS / 2);
    const float* xb = x + (size_t)b * C_ * NPTS;

    // fill roles
    const int fg   = ftile * 128 + wtid;
    const int vrow = (fg >> 5) * 63 + (fg & 31);
    const float* vre_p = vfre + (size_t)vrow * NPTS + kbase;
    const float* vim_p = vfim + (size_t)vrow * NPTS + kbase;
    const int   cc = wtid >> 1;
    const int   k8 = (wtid & 1) * 8;
    const float* xfill = xb + (size_t)cc * NPTS + kbase + k8;

    const int bar_id = wg + 1;

    for (int kb = 0; kb < NPTS / 2; kb += KC) {
        // A: one f-row per thread, 16 k values (re/im interleaved)
#pragma unroll
        for (int j = 0; j < 4; j++) {
            float4 r4 = *reinterpret_cast<const float4*>(vre_p + kb + 4 * j);
            float4 i4 = *reinterpret_cast<const float4*>(vim_p + kb + 4 * j);
            As[wg][4 * j + 0][wtid] = make_float2(r4.x, i4.x);
            As[wg][4 * j + 1][wtid] = make_float2(r4.y, i4.y);
            As[wg][4 * j + 2][wtid] = make_float2(r4.z, i4.z);
            As[wg][4 * j + 3][wtid] = make_float2(r4.w, i4.w);
        }
        // X: 8 k values for channel cc
        {
            float4 v0 = *reinterpret_cast<const float4*>(xfill + kb);
            float4 v1 = *reinterpret_cast<const float4*>(xfill + kb + 4);
            Xs[wg][k8 + 0][cc] = v0.x; Xs[wg][k8 + 1][cc] = v0.y;
            Xs[wg][k8 + 2][cc] = v0.z; Xs[wg][k8 + 3][cc] = v0.w;
            Xs[wg][k8 + 4][cc] = v1.x; Xs[wg][k8 + 5][cc] = v1.y;
            Xs[wg][k8 + 6][cc] = v1.z; Xs[wg][k8 + 7][cc] = v1.w;
        }
        WG_BAR(bar_id);

#pragma unroll 4
        for (int k = 0; k < KC; k++) {
            unsigned long long a[8];
            const ulonglong2* ap = reinterpret_cast<const ulonglong2*>(&As[wg][k][ty * 8]);
#pragma unroll
            for (int i = 0; i < 4; i++) { ulonglong2 t = ap[i]; a[2*i] = t.x; a[2*i+1] = t.y; }
            const float4* xp = reinterpret_cast<const float4*>(&Xs[wg][k][tx * 8]);
            float4 x0 = xp[0], x1 = xp[1];
            unsigned long long xv[8];
            xv[0] = pack2(x0.x, x0.x); xv[1] = pack2(x0.y, x0.y);
            xv[2] = pack2(x0.z, x0.z); xv[3] = pack2(x0.w, x0.w);
            xv[4] = pack2(x1.x, x1.x); xv[5] = pack2(x1.y, x1.y);
            xv[6] = pack2(x1.z, x1.z); xv[7] = pack2(x1.w, x1.w);
#pragma unroll
            for (int fi = 0; fi < 8; fi++)
#pragma unroll
                for (int ci = 0; ci < 8; ci++)
                    fma2(acc[fi][ci], a[fi], xv[ci]);
        }
        WG_BAR(bar_id);
    }

    // merge wg1 -> wg0 through smem (reuse As as scratch, 2 chunks of 32 accs)
    unsigned long long* scr = reinterpret_cast<unsigned long long*>(&As[0][0][0]);
#pragma unroll
    for (int ch = 0; ch < 2; ch++) {
        __syncthreads();
        if (wg == 1) {
#pragma unroll
            for (int j = 0; j < 32; j++) {
                int m = ch * 32 + j;
                scr[j * 128 + wtid] = acc[m >> 3][m & 7];
            }
        }
        __syncthreads();
        if (wg == 0) {
#pragma unroll
            for (int j = 0; j < 32; j++) {
                int m = ch * 32 + j;
                add2(acc[m >> 3][m & 7], scr[j * 128 + wtid]);
            }
        }
    }

    if (wg == 0) {
        const int f0 = ftile * 128 + ty * 8;
#pragma unroll
        for (int ci = 0; ci < 8; ci++) {
            int c = tx * 8 + ci;
            ulonglong2* dst = reinterpret_cast<ulonglong2*>(&g_Xft[((size_t)(b * C_ + c)) * F1 + f0]);
#pragma unroll
            for (int i = 0; i < 4; i++) {
                ulonglong2 t;
                t.x = acc[2 * i][ci];
                t.y = acc[2 * i + 1][ci];
                dst[i] = t;
            }
        }
    }
}

// ============================================================================
// Kernel 3: channel mixing + phi modulation + Hermitian expansion (unchanged).
// ============================================================================
__global__ __launch_bounds__(512) void k_mix(
    const float* __restrict__ w1re, const float* __restrict__ w1im,
    const float* __restrict__ w2re, const float* __restrict__ w2im)
{
    __shared__ float2 Xs[4][64][16];

    const int bid = blockIdx.x;
    const int xm  = bid >> 2;
    const int yh  = (bid >> 1) & 1;
    const int bh  = bid & 1;
    const int tid = threadIdx.x;

    {
        int row  = tid >> 1;
        int half = tid & 1;
        int br = row >> 6, ii = row & 63;
        const float2* src = g_Xft + ((size_t)((bh * 4 + br) * C_ + ii)) * F1
                            + xm * 32 + yh * 16 + half * 8;
#pragma unroll
        for (int j = 0; j < 4; j++) {
            float4 v = reinterpret_cast<const float4*>(src)[j];
            Xs[br][ii][half * 8 + j * 2]     = make_float2(v.x, v.y);
            Xs[br][ii][half * 8 + j * 2 + 1] = make_float2(v.z, v.w);
        }
    }
    __syncthreads();

    const int o   = tid >> 3;
    const int yq  = tid & 7;
    const int y   = yh * 16 + yq * 2;
    const int x32 = xm & 31;
    const float* wre = (xm < 32) ? w1re : w2re;
    const float* wim = (xm < 32) ? w1im : w2im;

    unsigned long long acc0[4] = {0ull, 0ull, 0ull, 0ull};
    unsigned long long acc1[4] = {0ull, 0ull, 0ull, 0ull};

#pragma unroll 4
    for (int ii = 0; ii < 64; ii++) {
        size_t wrow = (size_t)(ii * 64 + o) * 1024 + x32 * 32 + y;
        float2 wr = *reinterpret_cast<const float2*>(wre + wrow);
        float2 wi = *reinterpret_cast<const float2*>(wim + wrow);
        unsigned long long w0a = pack2(wr.x, wi.x);
        unsigned long long w0b = pack2(-wi.x, wr.x);
        unsigned long long w1a = pack2(wr.y, wi.y);
        unsigned long long w1b = pack2(-wi.y, wr.y);
#pragma unroll
        for (int br = 0; br < 4; br++) {
            float2 xv0 = Xs[br][ii][yq * 2];
            float2 xv1 = Xs[br][ii][yq * 2 + 1];
            fma2(acc0[br], pack2(xv0.x, xv0.x), w0a);
            fma2(acc0[br], pack2(xv0.y, xv0.y), w0b);
            fma2(acc1[br], pack2(xv1.x, xv1.x), w1a);
            fma2(acc1[br], pack2(xv1.y, xv1.y), w1b);
        }
    }

    const int sel = (xm < 32) ? 0 : 1;
#pragma unroll
    for (int br = 0; br < 4; br++) {
        int bb = bh * 4 + br;
#pragma unroll
        for (int pp = 0; pp < 2; pp++) {
            int yy = y + pp;
            float2 s = unpack2(pp ? acc1[br] : acc0[br]);
            float2 p = g_phi[sel * (B_ * 1024) + bb * 1024 + x32 * 32 + yy];
            float vr = p.x * s.x - p.y * s.y;
            float vi = p.x * s.y + p.y * s.x;
            int fm = xm * 32 + yy;
            g_xf[((size_t)(bb * C_ + o)) * MFRQ + fm] = make_float2(vr, -vi);
            if (fm >= 64)
                g_xf[((size_t)(bb * C_ + (63 - o))) * MFRQ + (4095 - fm)] = make_float2(vr, vi);
        }
    }
}

// ============================================================================
// Kernel 4: inverse NUFT (real part), K=4032, in-block split-K (2 x 2016).
// out[b,c,n] = (2/N) * sum_f (Vi_re*xf_re + Vi_im*(-xf_im))
// ============================================================================
__global__ __launch_bounds__(256, 1) void k_inverse(
    const float* __restrict__ vire,
    const float* __restrict__ viim,
    float* __restrict__ out)
{
    __shared__ float2 As[2][KC][128];  // 32 KB
    __shared__ float2 Xs[2][KC][C_];   // 16 KB  (total 48 KB)

    const int b     = blockIdx.y;
    const int ntile = blockIdx.x;
    const int tid   = threadIdx.x;
    const int wg    = tid >> 7;
    const int wtid  = tid & 127;
    const int tx    = wtid & 7;
    const int ty    = wtid >> 3;

    unsigned long long acc[8][8];
#pragma unroll
    for (int i = 0; i < 8; i++)
#pragma unroll
        for (int j = 0; j < 8; j++) acc[i][j] = 0ull;

    const int kbase = wg * (MFRQ / 2);   // 2016

    const int row = ntile * 128 + wtid;
    const float* vre_p = vire + (size_t)row * MFRQ + kbase;
    const float* vim_p = viim + (size_t)row * MFRQ + kbase;
    const int cc = wtid >> 1;
    const int k8 = (wtid & 1) * 8;
    const float2* xsrc = g_xf + ((size_t)(b * C_ + cc)) * MFRQ + kbase + k8;

    const int bar_id = wg + 1;

    for (int kb = 0; kb < MFRQ / 2; kb += KC) {
#pragma unroll
        for (int j = 0; j < 4; j++) {
            float4 r4 = *reinterpret_cast<const float4*>(vre_p + kb + 4 * j);
            float4 i4 = *reinterpret_cast<const float4*>(vim_p + kb + 4 * j);
            As[wg][4 * j + 0][wtid] = make_float2(r4.x, i4.x);
            As[wg][4 * j + 1][wtid] = make_float2(r4.y, i4.y);
            As[wg][4 * j + 2][wtid] = make_float2(r4.z, i4.z);
            As[wg][4 * j + 3][wtid] = make_float2(r4.w, i4.w);
        }
#pragma unroll
        for (int j = 0; j < 4; j++) {
            float4 v = *reinterpret_cast<const float4*>(xsrc + kb + 2 * j);
            Xs[wg][k8 + 2 * j][cc]     = make_float2(v.x, v.y);
            Xs[wg][k8 + 2 * j + 1][cc] = make_float2(v.z, v.w);
        }
        WG_BAR(bar_id);

#pragma unroll 4
        for (int k = 0; k < KC; k++) {
            unsigned long long a[8], xv[8];
            const ulonglong2* ap = reinterpret_cast<const ulonglong2*>(&As[wg][k][ty * 8]);
#pragma unroll
            for (int i = 0; i < 4; i++) { ulonglong2 t = ap[i]; a[2*i] = t.x; a[2*i+1] = t.y; }
            const ulonglong2* xp = reinterpret_cast<const ulonglong2*>(&Xs[wg][k][tx * 8]);
#pragma unroll
            for (int i = 0; i < 4; i++) { ulonglong2 t = xp[i]; xv[2*i] = t.x; xv[2*i+1] = t.y; }
#pragma unroll
            for (int fi = 0; fi < 8; fi++)
#pragma unroll
                for (int ci = 0; ci < 8; ci++)
                    fma2(acc[fi][ci], a[fi], xv[ci]);
        }
        WG_BAR(bar_id);
    }

    // merge wg1 -> wg0
    unsigned long long* scr = reinterpret_cast<unsigned long long*>(&As[0][0][0]);
#pragma unroll
    for (int ch = 0; ch < 2; ch++) {
        __syncthreads();
        if (wg == 1) {
#pragma unroll
            for (int j = 0; j < 32; j++) {
                int m = ch * 32 + j;
                scr[j * 128 + wtid] = acc[m >> 3][m & 7];
            }
        }
        __syncthreads();
        if (wg == 0) {
#pragma unroll
            for (int j = 0; j < 32; j++) {
                int m = ch * 32 + j;
                add2(acc[m >> 3][m & 7], scr[j * 128 + wtid]);
            }
        }
    }

    if (wg == 0) {
        const float sc = 2.0f / (float)NPTS;
        const int n0 = ntile * 128 + ty * 8;
#pragma unroll
        for (int ci = 0; ci < 8; ci++) {
            int c = tx * 8 + ci;
            float r[8];
#pragma unroll
            for (int fi = 0; fi < 8; fi++) {
                float2 s = unpack2(acc[fi][ci]);
                r[fi] = (s.x + s.y) * sc;
            }
            float4* dst = reinterpret_cast<float4*>(out + ((size_t)(b * C_ + c)) * NPTS + n0);
            dst[0] = make_float4(r[0], r[1], r[2], r[3]);
            dst[1] = make_float4(r[4], r[5], r[6], r[7]);
        }
    }
}

// ============================================================================
extern "C" void kernel_launch(void* const* d_in, const int* in_sizes, int n_in,
                              void* d_out, int out_size)
{
    const float* x     = (const float*)d_in[0];
    const float* emb   = (const float*)d_in[1];
    const float* vf_re = (const float*)d_in[2];
    const float* vf_im = (const float*)d_in[3];
    const float* vi_re = (const float*)d_in[4];
    const float* vi_im = (const float*)d_in[5];
    const float* w1_re = (const float*)d_in[6];
    const float* w1_im = (const float*)d_in[7];
    const float* w2_re = (const float*)d_in[8];
    const float* w2_im = (const float*)d_in[9];
    const float* m1_re = (const float*)d_in[10];
    const float* m1_im = (const float*)d_in[11];
    const float* m2_re = (const float*)d_in[12];
    const float* m2_im = (const float*)d_in[13];
    float* out = (float*)d_out;

    k_phi<<<2048, 256>>>(emb, m1_re, m1_im, m2_re, m2_im);
    k_forward<<<dim3(16, 8), 256>>>(x, vf_re, vf_im);
    k_mix<<<256, 512>>>(w1_re, w1_im, w2_re, w2_im);
    k_inverse<<<dim3(16, 8), 256>>>(vi_re, vi_im, out);
}

// round 6
// speedup vs baseline: 1.7037x; 1.1992x over previous
#include <cuda_runtime.h>

#define B_   8
#define C_   64
#define NPTS 2048
#define MFRQ 4032
#define F1   2048
#define KC   16

// -------- scratch (device globals; no allocation in kernel_launch) ----------
__device__ __align__(16) float2 g_Xft[B_ * C_ * F1];   // forward result {re, im},  [b][c][f]
__device__ __align__(16) float2 g_xf [B_ * MFRQ * C_]; // Hermitian-expanded {re, -im}, [b][f][c]
__device__ __align__(16) float  g_xT [B_ * NPTS * C_]; // x transposed [b][n][c]
__device__ float2 g_phi[2 * B_ * 1024];                // [mod][b][x(32)][y(32)]

// -------- packed f32x2 helpers ----------------------------------------------
__device__ __forceinline__ unsigned long long pack2(float lo, float hi) {
    unsigned long long r;
    asm("mov.b64 %0, {%1, %2};" : "=l"(r) : "f"(lo), "f"(hi));
    return r;
}
__device__ __forceinline__ float2 unpack2(unsigned long long v) {
    float2 r;
    asm("mov.b64 {%0, %1}, %2;" : "=f"(r.x), "=f"(r.y) : "l"(v));
    return r;
}
__device__ __forceinline__ void fma2(unsigned long long &d,
                                     unsigned long long a,
                                     unsigned long long b) {
    asm("fma.rn.f32x2 %0, %1, %2, %0;" : "+l"(d) : "l"(a), "l"(b));
}
__device__ __forceinline__ void add2(unsigned long long &d, unsigned long long a) {
    asm("add.rn.f32x2 %0, %0, %1;" : "+l"(d) : "l"(a));
}
#define WG_BAR(id) asm volatile("bar.sync %0, 128;" :: "r"(id) : "memory")

// ============================================================================
// Kernel 0: transpose x[b][c][n] -> g_xT[b][n][c]
// ============================================================================
__global__ __launch_bounds__(256) void k_transpose(const float* __restrict__ x)
{
    __shared__ float t[64][65];
    const int b   = blockIdx.y;
    const int n0  = blockIdx.x * 64;
    const int tid = threadIdx.x;

    {
        const int c  = tid >> 2;
        const int nq = (tid & 3) * 16;
        const float4* src = reinterpret_cast<const float4*>(
            x + ((size_t)(b * C_ + c)) * NPTS + n0 + nq);
#pragma unroll
        for (int j = 0; j < 4; j++) {
            float4 v = src[j];
            t[c][nq + 4 * j + 0] = v.x;
            t[c][nq + 4 * j + 1] = v.y;
            t[c][nq + 4 * j + 2] = v.z;
            t[c][nq + 4 * j + 3] = v.w;
        }
    }
    __syncthreads();
    {
        const int n  = tid >> 2;
        const int cq = (tid & 3) * 16;
        float4* dst = reinterpret_cast<float4*>(
            g_xT + ((size_t)(b * NPTS + n0 + n)) * C_ + cq);
#pragma unroll
        for (int j = 0; j < 4; j++) {
            float4 v;
            v.x = t[cq + 4 * j + 0][n];
            v.y = t[cq + 4 * j + 1][n];
            v.z = t[cq + 4 * j + 2][n];
            v.w = t[cq + 4 * j + 3][n];
            dst[j] = v;
        }
    }
}

// ============================================================================
// Kernel 1: phi[b,x,y] = sum_e mod[x,y,e] * emb[b,e]
// ============================================================================
__global__ __launch_bounds__(256) void k_phi(
    const float* __restrict__ emb,
    const float* __restrict__ m1re, const float* __restrict__ m1im,
    const float* __restrict__ m2re, const float* __restrict__ m2im)
{
    __shared__ float s_re[256];
    __shared__ float s_im[256];
    const int bid = blockIdx.x;
    const int mod = bid >> 10;
    const int xy  = bid & 1023;
    const int tid = threadIdx.x;

    const float* mre = (mod ? m2re : m1re) + (size_t)xy * 256;
    const float* mim = (mod ? m2im : m1im) + (size_t)xy * 256;
    s_re[tid] = mre[tid];
    s_im[tid] = mim[tid];
    __syncthreads();

    const int w = tid >> 5;
    const int l = tid & 31;
    float pr = 0.f, pi = 0.f;
#pragma unroll
    for (int j = 0; j < 8; j++) {
        int e = l + j * 32;
        float ee = emb[w * 256 + e];
        pr += s_re[e] * ee;
        pi += s_im[e] * ee;
    }
#pragma unroll
    for (int off = 16; off > 0; off >>= 1) {
        pr += __shfl_down_sync(0xffffffffu, pr, off);
        pi += __shfl_down_sync(0xffffffffu, pi, off);
    }
    if (l == 0) g_phi[mod * (B_ * 1024) + w * 1024 + xy] = make_float2(pr, pi);
}

// ============================================================================
// Kernel 2: forward NUFT, split-K, conflict-free swizzled smem.
// A chunk(ty,i,k) = {re(f0),im(f0),re(f1),im(f1)}, f0=ty*8+2i, at byte
//   k*1024 + i*256 + ((ty+k)&15)*16.
// X chunk(tx,i,k) = 4 floats c=tx*8+i*4.., at byte k*256 + i*128 + ((tx+k)&7)*16.
// ============================================================================
__global__ __launch_bounds__(256, 1) void k_forward(
    const float* __restrict__ vfre,
    const float* __restrict__ vfim)
{
    __shared__ __align__(16) char sA[2][KC * 1024];  // 32 KB
    __shared__ __align__(16) char sX[2][KC * 256];   // 8 KB

    const int b     = blockIdx.y;
    const int ftile = blockIdx.x;
    const int tid   = threadIdx.x;
    const int wg    = tid >> 7;
    const int wtid  = tid & 127;
    const int tx    = wtid & 7;
    const int ty    = wtid >> 3;

    unsigned long long acc[8][8];
#pragma unroll
    for (int i = 0; i < 8; i++)
#pragma unroll
        for (int j = 0; j < 8; j++) acc[i][j] = 0ull;

    const int kbase = wg * (NPTS / 2);

    // A fill role: thread owns f-pair fp, k-half k8
    const int fp  = wtid >> 1;
    const int k8  = (wtid & 1) * 8;
    const int fg0 = ftile * 128 + 2 * fp;
    const int fg1 = fg0 + 1;
    const int row0 = (fg0 >> 5) * 63 + (fg0 & 31);
    const int row1 = (fg1 >> 5) * 63 + (fg1 & 31);
    const float* pr0 = vfre + (size_t)row0 * NPTS + kbase + k8;
    const float* pi0 = vfim + (size_t)row0 * NPTS + kbase + k8;
    const float* pr1 = vfre + (size_t)row1 * NPTS + kbase + k8;
    const float* pi1 = vfim + (size_t)row1 * NPTS + kbase + k8;
    char* Afill = sA[wg] + (fp & 3) * 256;
    const int ftyp = fp >> 2;

    // X fill role: thread owns k-row kx, chunk-quad qx
    const int kx = wtid >> 3;
    const int qx = wtid & 7;
    const float* xsrc = g_xT + ((size_t)(b * NPTS) + kbase + kx) * C_ + qx * 8;
    char* Xfill = sX[wg] + kx * 256;
    const int xswf = ((qx + kx) & 7) * 16;

    const int bar_id = wg + 1;

    for (int kb = 0; kb < NPTS / 2; kb += KC) {
        // ---- fill A ----
        {
            float4 a0 = *reinterpret_cast<const float4*>(pr0 + kb);
            float4 a1 = *reinterpret_cast<const float4*>(pr0 + kb + 4);
            float4 b0 = *reinterpret_cast<const float4*>(pi0 + kb);
            float4 b1 = *reinterpret_cast<const float4*>(pi0 + kb + 4);
            float4 c0 = *reinterpret_cast<const float4*>(pr1 + kb);
            float4 c1 = *reinterpret_cast<const float4*>(pr1 + kb + 4);
            float4 d0 = *reinterpret_cast<const float4*>(pi1 + kb);
            float4 d1 = *reinterpret_cast<const float4*>(pi1 + kb + 4);
            float r0[8] = {a0.x,a0.y,a0.z,a0.w,a1.x,a1.y,a1.z,a1.w};
            float q0[8] = {b0.x,b0.y,b0.z,b0.w,b1.x,b1.y,b1.z,b1.w};
            float r1[8] = {c0.x,c0.y,c0.z,c0.w,c1.x,c1.y,c1.z,c1.w};
            float q1[8] = {d0.x,d0.y,d0.z,d0.w,d1.x,d1.y,d1.z,d1.w};
#pragma unroll
            for (int j = 0; j < 8; j++) {
                int kk = k8 + j;
                *reinterpret_cast<float4*>(Afill + kk * 1024 + ((ftyp + kk) & 15) * 16)
                    = make_float4(r0[j], q0[j], r1[j], q1[j]);
            }
        }
        // ---- fill X ----
#pragma unroll
        for (int j = 0; j < 2; j++) {
            float4 v = *reinterpret_cast<const float4*>(xsrc + (size_t)kb * C_ + j * 4);
            *reinterpret_cast<float4*>(Xfill + j * 128 + xswf) = v;
        }
        WG_BAR(bar_id);

#pragma unroll 4
        for (int kk = 0; kk < KC; kk++) {
            const char* Ab = sA[wg] + kk * 1024;
            const int asw = ((ty + kk) & 15) * 16;
            unsigned long long a[8];
#pragma unroll
            for (int i = 0; i < 4; i++) {
                ulonglong2 t = *reinterpret_cast<const ulonglong2*>(Ab + i * 256 + asw);
                a[2 * i] = t.x; a[2 * i + 1] = t.y;
            }
            const char* Xb = sX[wg] + kk * 256;
            const int xsw = ((tx + kk) & 7) * 16;
            float4 x0 = *reinterpret_cast<const float4*>(Xb + xsw);
            float4 x1 = *reinterpret_cast<const float4*>(Xb + 128 + xsw);
            unsigned long long xv[8];
            xv[0] = pack2(x0.x, x0.x); xv[1] = pack2(x0.y, x0.y);
            xv[2] = pack2(x0.z, x0.z); xv[3] = pack2(x0.w, x0.w);
            xv[4] = pack2(x1.x, x1.x); xv[5] = pack2(x1.y, x1.y);
            xv[6] = pack2(x1.z, x1.z); xv[7] = pack2(x1.w, x1.w);
#pragma unroll
            for (int fi = 0; fi < 8; fi++)
#pragma unroll
                for (int ci = 0; ci < 8; ci++)
                    fma2(acc[fi][ci], a[fi], xv[ci]);
        }
        WG_BAR(bar_id);
    }

    // merge wg1 -> wg0 through smem (reuse sA)
    unsigned long long* scr = reinterpret_cast<unsigned long long*>(&sA[0][0]);
#pragma unroll
    for (int ch = 0; ch < 2; ch++) {
        __syncthreads();
        if (wg == 1) {
#pragma unroll
            for (int j = 0; j < 32; j++) {
                int m = ch * 32 + j;
                scr[j * 128 + wtid] = acc[m >> 3][m & 7];
            }
        }
        __syncthreads();
        if (wg == 0) {
#pragma unroll
            for (int j = 0; j < 32; j++) {
                int m = ch * 32 + j;
                add2(acc[m >> 3][m & 7], scr[j * 128 + wtid]);
            }
        }
    }

    if (wg == 0) {
        const int f0 = ftile * 128 + ty * 8;
#pragma unroll
        for (int ci = 0; ci < 8; ci++) {
            int c = tx * 8 + ci;
            ulonglong2* dst = reinterpret_cast<ulonglong2*>(&g_Xft[((size_t)(b * C_ + c)) * F1 + f0]);
#pragma unroll
            for (int i = 0; i < 4; i++) {
                ulonglong2 t;
                t.x = acc[2 * i][ci];
                t.y = acc[2 * i + 1][ci];
                dst[i] = t;
            }
        }
    }
}

// ============================================================================
// Kernel 3: channel mixing + phi modulation + Hermitian expansion.
// g_xf now [b][f][c].
// ============================================================================
__global__ __launch_bounds__(512) void k_mix(
    const float* __restrict__ w1re, const float* __restrict__ w1im,
    const float* __restrict__ w2re, const float* __restrict__ w2im)
{
    __shared__ float2 Xs[4][64][16];

    const int bid = blockIdx.x;
    const int xm  = bid >> 2;
    const int yh  = (bid >> 1) & 1;
    const int bh  = bid & 1;
    const int tid = threadIdx.x;

    {
        int row  = tid >> 1;
        int half = tid & 1;
        int br = row >> 6, ii = row & 63;
        const float2* src = g_Xft + ((size_t)((bh * 4 + br) * C_ + ii)) * F1
                            + xm * 32 + yh * 16 + half * 8;
#pragma unroll
        for (int j = 0; j < 4; j++) {
            float4 v = reinterpret_cast<const float4*>(src)[j];
            Xs[br][ii][half * 8 + j * 2]     = make_float2(v.x, v.y);
            Xs[br][ii][half * 8 + j * 2 + 1] = make_float2(v.z, v.w);
        }
    }
    __syncthreads();

    const int o   = tid >> 3;
    const int yq  = tid & 7;
    const int y   = yh * 16 + yq * 2;
    const int x32 = xm & 31;
    const float* wre = (xm < 32) ? w1re : w2re;
    const float* wim = (xm < 32) ? w1im : w2im;

    unsigned long long acc0[4] = {0ull, 0ull, 0ull, 0ull};
    unsigned long long acc1[4] = {0ull, 0ull, 0ull, 0ull};

#pragma unroll 4
    for (int ii = 0; ii < 64; ii++) {
        size_t wrow = (size_t)(ii * 64 + o) * 1024 + x32 * 32 + y;
        float2 wr = *reinterpret_cast<const float2*>(wre + wrow);
        float2 wi = *reinterpret_cast<const float2*>(wim + wrow);
        unsigned long long w0a = pack2(wr.x, wi.x);
        unsigned long long w0b = pack2(-wi.x, wr.x);
        unsigned long long w1a = pack2(wr.y, wi.y);
        unsigned long long w1b = pack2(-wi.y, wr.y);
#pragma unroll
        for (int br = 0; br < 4; br++) {
            float2 xv0 = Xs[br][ii][yq * 2];
            float2 xv1 = Xs[br][ii][yq * 2 + 1];
            fma2(acc0[br], pack2(xv0.x, xv0.x), w0a);
            fma2(acc0[br], pack2(xv0.y, xv0.y), w0b);
            fma2(acc1[br], pack2(xv1.x, xv1.x), w1a);
            fma2(acc1[br], pack2(xv1.y, xv1.y), w1b);
        }
    }

    const int sel = (xm < 32) ? 0 : 1;
#pragma unroll
    for (int br = 0; br < 4; br++) {
        int bb = bh * 4 + br;
#pragma unroll
        for (int pp = 0; pp < 2; pp++) {
            int yy = y + pp;
            float2 s = unpack2(pp ? acc1[br] : acc0[br]);
            float2 p = g_phi[sel * (B_ * 1024) + bb * 1024 + x32 * 32 + yy];
            float vr = p.x * s.x - p.y * s.y;
            float vi = p.x * s.y + p.y * s.x;
            int fm = xm * 32 + yy;
            g_xf[((size_t)bb * MFRQ + fm) * C_ + o] = make_float2(vr, -vi);
            if (fm >= 64)
                g_xf[((size_t)bb * MFRQ + (4095 - fm)) * C_ + (63 - o)] = make_float2(vr, vi);
        }
    }
}

// ============================================================================
// Kernel 4: inverse NUFT (real part), K=4032, split-K, swizzled smem.
// X chunk(tx,i,k) = float2 pair c=tx*8+2i,+1 at k*512 + i*128 + ((tx+k)&7)*16.
// ============================================================================
__global__ __launch_bounds__(256, 1) void k_inverse(
    const float* __restrict__ vire,
    const float* __restrict__ viim,
    float* __restrict__ out)
{
    __shared__ __align__(16) char sA[2][KC * 1024];  // 32 KB
    __shared__ __align__(16) char sX[2][KC * 512];   // 16 KB

    const int b     = blockIdx.y;
    const int ntile = blockIdx.x;
    const int tid   = threadIdx.x;
    const int wg    = tid >> 7;
    const int wtid  = tid & 127;
    const int tx    = wtid & 7;
    const int ty    = wtid >> 3;

    unsigned long long acc[8][8];
#pragma unroll
    for (int i = 0; i < 8; i++)
#pragma unroll
        for (int j = 0; j < 8; j++) acc[i][j] = 0ull;

    const int kbase = wg * (MFRQ / 2);   // 2016

    // A fill role
    const int fp  = wtid >> 1;
    const int k8  = (wtid & 1) * 8;
    const int row0 = ntile * 128 + 2 * fp;
    const float* pr0 = vire + (size_t)row0 * MFRQ + kbase + k8;
    const float* pi0 = viim + (size_t)row0 * MFRQ + kbase + k8;
    const float* pr1 = pr0 + MFRQ;
    const float* pi1 = pi0 + MFRQ;
    char* Afill = sA[wg] + (fp & 3) * 256;
    const int ftyp = fp >> 2;

    // X fill role
    const int kx = wtid >> 3;
    const int qx = wtid & 7;
    const float2* xsrc = g_xf + ((size_t)(b * MFRQ) + kbase + kx) * C_ + qx * 8;
    char* Xfill = sX[wg] + kx * 512;
    const int xswf = ((qx + kx) & 7) * 16;

    const int bar_id = wg + 1;

    for (int kb = 0; kb < MFRQ / 2; kb += KC) {
        // ---- fill A ----
        {
            float4 a0 = *reinterpret_cast<const float4*>(pr0 + kb);
            float4 a1 = *reinterpret_cast<const float4*>(pr0 + kb + 4);
            float4 b0 = *reinterpret_cast<const float4*>(pi0 + kb);
            float4 b1 = *reinterpret_cast<const float4*>(pi0 + kb + 4);
            float4 c0 = *reinterpret_cast<const float4*>(pr1 + kb);
            float4 c1 = *reinterpret_cast<const float4*>(pr1 + kb + 4);
            float4 d0 = *reinterpret_cast<const float4*>(pi1 + kb);
            float4 d1 = *reinterpret_cast<const float4*>(pi1 + kb + 4);
            float r0[8] = {a0.x,a0.y,a0.z,a0.w,a1.x,a1.y,a1.z,a1.w};
            float q0[8] = {b0.x,b0.y,b0.z,b0.w,b1.x,b1.y,b1.z,b1.w};
            float r1[8] = {c0.x,c0.y,c0.z,c0.w,c1.x,c1.y,c1.z,c1.w};
            float q1[8] = {d0.x,d0.y,d0.z,d0.w,d1.x,d1.y,d1.z,d1.w};
#pragma unroll
            for (int j = 0; j < 8; j++) {
                int kk = k8 + j;
                *reinterpret_cast<float4*>(Afill + kk * 1024 + ((ftyp + kk) & 15) * 16)
                    = make_float4(r0[j], q0[j], r1[j], q1[j]);
            }
        }
        // ---- fill X ----
#pragma unroll
        for (int j = 0; j < 4; j++) {
            float4 v = *reinterpret_cast<const float4*>(xsrc + (size_t)kb * C_ + j * 2);
            *reinterpret_cast<float4*>(Xfill + j * 128 + xswf) = v;
        }
        WG_BAR(bar_id);

#pragma unroll 4
        for (int kk = 0; kk < KC; kk++) {
            const char* Ab = sA[wg] + kk * 1024;
            const int asw = ((ty + kk) & 15) * 16;
            unsigned long long a[8];
#pragma unroll
            for (int i = 0; i < 4; i++) {
                ulonglong2 t = *reinterpret_cast<const ulonglong2*>(Ab + i * 256 + asw);
                a[2 * i] = t.x; a[2 * i + 1] = t.y;
            }
            const char* Xb = sX[wg] + kk * 512;
            const int xsw = ((tx + kk) & 7) * 16;
            unsigned long long xv[8];
#pragma unroll
            for (int i = 0; i < 4; i++) {
                ulonglong2 t = *reinterpret_cast<const ulonglong2*>(Xb + i * 128 + xsw);
                xv[2 * i] = t.x; xv[2 * i + 1] = t.y;
            }
#pragma unroll
            for (int fi = 0; fi < 8; fi++)
#pragma unroll
                for (int ci = 0; ci < 8; ci++)
                    fma2(acc[fi][ci], a[fi], xv[ci]);
        }
        WG_BAR(bar_id);
    }

    // merge wg1 -> wg0
    unsigned long long* scr = reinterpret_cast<unsigned long long*>(&sA[0][0]);
#pragma unroll
    for (int ch = 0; ch < 2; ch++) {
        __syncthreads();
        if (wg == 1) {
#pragma unroll
            for (int j = 0; j < 32; j++) {
                int m = ch * 32 + j;
                scr[j * 128 + wtid] = acc[m >> 3][m & 7];
            }
        }
        __syncthreads();
        if (wg == 0) {
#pragma unroll
            for (int j = 0; j < 32; j++) {
                int m = ch * 32 + j;
                add2(acc[m >> 3][m & 7], scr[j * 128 + wtid]);
            }
        }
    }

    if (wg == 0) {
        const float sc = 2.0f / (float)NPTS;
        const int n0 = ntile * 128 + ty * 8;
#pragma unroll
        for (int ci = 0; ci < 8; ci++) {
            int c = tx * 8 + ci;
            float r[8];
#pragma unroll
            for (int fi = 0; fi < 8; fi++) {
                float2 s = unpack2(acc[fi][ci]);
                r[fi] = (s.x + s.y) * sc;
            }
            float4* dst = reinterpret_cast<float4*>(out + ((size_t)(b * C_ + c)) * NPTS + n0);
            dst[0] = make_float4(r[0], r[1], r[2], r[3]);
            dst[1] = make_float4(r[4], r[5], r[6], r[7]);
        }
    }
}

// ============================================================================
extern "C" void kernel_launch(void* const* d_in, const int* in_sizes, int n_in,
                              void* d_out, int out_size)
{
    const float* x     = (const float*)d_in[0];
    const float* emb   = (const float*)d_in[1];
    const float* vf_re = (const float*)d_in[2];
    const float* vf_im = (const float*)d_in[3];
    const float* vi_re = (const float*)d_in[4];
    const float* vi_im = (const float*)d_in[5];
    const float* w1_re = (const float*)d_in[6];
    const float* w1_im = (const float*)d_in[7];
    const float* w2_re = (const float*)d_in[8];
    const float* w2_im = (const float*)d_in[9];
    const float* m1_re = (const float*)d_in[10];
    const float* m1_im = (const float*)d_in[11];
    const float* m2_re = (const float*)d_in[12];
    const float* m2_im = (const float*)d_in[13];
    float* out = (float*)d_out;

    k_phi<<<2048, 256>>>(emb, m1_re, m1_im, m2_re, m2_im);
    k_transpose<<<dim3(32, 8), 256>>>(x);
    k_forward<<<dim3(16, 8), 256>>>(vf_re, vf_im);
    k_mix<<<256, 512>>>(w1_re, w1_im, w2_re, w2_im);
    k_inverse<<<dim3(16, 8), 256>>>(vi_re, vi_im, out);
}

// round 7
// speedup vs baseline: 2.3439x; 1.3758x over previous
#include <cuda_runtime.h>

#define B_   8
#define C_   64
#define NPTS 2048
#define MFRQ 4032
#define F1   2048
#define KC   8

// -------- scratch (device globals; no allocation in kernel_launch) ----------
__device__ __align__(16) float2 g_Xft[B_ * C_ * F1];   // forward result {re, im},  [b][c][f]
__device__ __align__(16) float2 g_xf [B_ * MFRQ * C_]; // Hermitian-expanded {re, -im}, [b][f][c]
__device__ __align__(16) float  g_xT [B_ * NPTS * C_]; // x transposed [b][n][c]
__device__ float2 g_phi[2 * B_ * 1024];                // [mod][b][x(32)][y(32)]

// -------- packed f32x2 helpers ----------------------------------------------
__device__ __forceinline__ unsigned long long pack2(float lo, float hi) {
    unsigned long long r;
    asm("mov.b64 %0, {%1, %2};" : "=l"(r) : "f"(lo), "f"(hi));
    return r;
}
__device__ __forceinline__ float2 unpack2(unsigned long long v) {
    float2 r;
    asm("mov.b64 {%0, %1}, %2;" : "=f"(r.x), "=f"(r.y) : "l"(v));
    return r;
}
__device__ __forceinline__ void fma2(unsigned long long &d,
                                     unsigned long long a,
                                     unsigned long long b) {
    asm("fma.rn.f32x2 %0, %1, %2, %0;" : "+l"(d) : "l"(a), "l"(b));
}
__device__ __forceinline__ void add2(unsigned long long &d, unsigned long long a) {
    asm("add.rn.f32x2 %0, %0, %1;" : "+l"(d) : "l"(a));
}
#define WG_BAR(id) asm volatile("bar.sync %0, 128;" :: "r"(id) : "memory")

// ============================================================================
// Kernel 0: transpose x[b][c][n] -> g_xT[b][n][c]
// ============================================================================
__global__ __launch_bounds__(256) void k_transpose(const float* __restrict__ x)
{
    __shared__ float t[64][65];
    const int b   = blockIdx.y;
    const int n0  = blockIdx.x * 64;
    const int tid = threadIdx.x;

    {
        const int c  = tid >> 2;
        const int nq = (tid & 3) * 16;
        const float4* src = reinterpret_cast<const float4*>(
            x + ((size_t)(b * C_ + c)) * NPTS + n0 + nq);
#pragma unroll
        for (int j = 0; j < 4; j++) {
            float4 v = src[j];
            t[c][nq + 4 * j + 0] = v.x;
            t[c][nq + 4 * j + 1] = v.y;
            t[c][nq + 4 * j + 2] = v.z;
            t[c][nq + 4 * j + 3] = v.w;
        }
    }
    __syncthreads();
    {
        const int n  = tid >> 2;
        const int cq = (tid & 3) * 16;
        float4* dst = reinterpret_cast<float4*>(
            g_xT + ((size_t)(b * NPTS + n0 + n)) * C_ + cq);
#pragma unroll
        for (int j = 0; j < 4; j++) {
            float4 v;
            v.x = t[cq + 4 * j + 0][n];
            v.y = t[cq + 4 * j + 1][n];
            v.z = t[cq + 4 * j + 2][n];
            v.w = t[cq + 4 * j + 3][n];
            dst[j] = v;
        }
    }
}

// ============================================================================
// Kernel 1: phi[b,x,y] = sum_e mod[x,y,e] * emb[b,e]
// ============================================================================
__global__ __launch_bounds__(256) void k_phi(
    const float* __restrict__ emb,
    const float* __restrict__ m1re, const float* __restrict__ m1im,
    const float* __restrict__ m2re, const float* __restrict__ m2im)
{
    __shared__ float s_re[256];
    __shared__ float s_im[256];
    const int bid = blockIdx.x;
    const int mod = bid >> 10;
    const int xy  = bid & 1023;
    const int tid = threadIdx.x;

    const float* mre = (mod ? m2re : m1re) + (size_t)xy * 256;
    const float* mim = (mod ? m2im : m1im) + (size_t)xy * 256;
    s_re[tid] = mre[tid];
    s_im[tid] = mim[tid];
    __syncthreads();

    const int w = tid >> 5;
    const int l = tid & 31;
    float pr = 0.f, pi = 0.f;
#pragma unroll
    for (int j = 0; j < 8; j++) {
        int e = l + j * 32;
        float ee = emb[w * 256 + e];
        pr += s_re[e] * ee;
        pi += s_im[e] * ee;
    }
#pragma unroll
    for (int off = 16; off > 0; off >>= 1) {
        pr += __shfl_down_sync(0xffffffffu, pr, off);
        pi += __shfl_down_sync(0xffffffffu, pi, off);
    }
    if (l == 0) g_phi[mod * (B_ * 1024) + w * 1024 + xy] = make_float2(pr, pi);
}

// ============================================================================
// Kernel 2: forward NUFT, split-K, 2-stage pipelined, swizzled smem.
// A chunk(i,k): f-pair (ty*4+i) at k*1024 + i*256 + ((ty+k)&15)*16.
// X chunk(i,k): 4 floats c=tx*8+4i at k*256 + i*128 + ((tx+k)&7)*16.
// ============================================================================
__global__ __launch_bounds__(256, 1) void k_forward(
    const float* __restrict__ vfre,
    const float* __restrict__ vfim)
{
    __shared__ __align__(16) char sA[2][2][KC * 1024];  // [wg][stage] 32 KB
    __shared__ __align__(16) char sX[2][2][KC * 256];   // [wg][stage]  8 KB

    const int b     = blockIdx.y;
    const int ftile = blockIdx.x;
    const int tid   = threadIdx.x;
    const int wg    = tid >> 7;
    const int wtid  = tid & 127;
    const int tx    = wtid & 7;
    const int ty    = wtid >> 3;

    unsigned long long acc[8][8];
#pragma unroll
    for (int i = 0; i < 8; i++)
#pragma unroll
        for (int j = 0; j < 8; j++) acc[i][j] = 0ull;

    const int KHALF = NPTS / 2;
    const int kbase = wg * KHALF;

    // A fill role: f-pair fp, k-quarter kh (0 or 4)
    const int fp  = wtid >> 1;
    const int kh  = (wtid & 1) * 4;
    const int fg0 = ftile * 128 + 2 * fp;
    const int fg1 = fg0 + 1;
    const int row0 = (fg0 >> 5) * 63 + (fg0 & 31);
    const int row1 = (fg1 >> 5) * 63 + (fg1 & 31);
    const float* pr0 = vfre + (size_t)row0 * NPTS + kbase + kh;
    const float* pi0 = vfim + (size_t)row0 * NPTS + kbase + kh;
    const float* pr1 = vfre + (size_t)row1 * NPTS + kbase + kh;
    const float* pi1 = vfim + (size_t)row1 * NPTS + kbase + kh;
    const int aoff = (fp & 3) * 256;       // i slot
    const int ftyp = fp >> 2;

    // X fill role: k-row kx (0..7), sub covers (j = sub>>3, qx = sub&7)
    const int kx  = wtid >> 4;
    const int sub = wtid & 15;
    const int qxf = sub & 7;
    const int jf  = sub >> 3;
    const float* xsrc = g_xT + ((size_t)(b * NPTS) + kbase + kx) * C_ + qxf * 8 + 4 * jf;
    const int xoff = jf * 128 + ((qxf + kx) & 7) * 16;

    const int bar_id = wg + 1;

    // prefetch kb = 0
    float4 pa0 = *reinterpret_cast<const float4*>(pr0);
    float4 pb0 = *reinterpret_cast<const float4*>(pi0);
    float4 pc0 = *reinterpret_cast<const float4*>(pr1);
    float4 pd0 = *reinterpret_cast<const float4*>(pi1);
    float4 pxv = *reinterpret_cast<const float4*>(xsrc);

    int stage = 0;
    for (int kb = 0; kb < KHALF; kb += KC) {
        // ---- store prefetched regs into smem[stage] ----
        {
            char* Abase = sA[wg][stage] + aoff;
            float r[4] = {pa0.x, pa0.y, pa0.z, pa0.w};
            float q[4] = {pb0.x, pb0.y, pb0.z, pb0.w};
            float s[4] = {pc0.x, pc0.y, pc0.z, pc0.w};
            float u[4] = {pd0.x, pd0.y, pd0.z, pd0.w};
#pragma unroll
            for (int j = 0; j < 4; j++) {
                int kk = kh + j;
                *reinterpret_cast<float4*>(Abase + kk * 1024 + ((ftyp + kk) & 15) * 16)
                    = make_float4(r[j], q[j], s[j], u[j]);
            }
            *reinterpret_cast<float4*>(sX[wg][stage] + kx * 256 + xoff) = pxv;
        }
        // ---- prefetch next block (LDG issues early, hidden by compute) ----
        if (kb + KC < KHALF) {
            pa0 = *reinterpret_cast<const float4*>(pr0 + kb + KC);
            pb0 = *reinterpret_cast<const float4*>(pi0 + kb + KC);
            pc0 = *reinterpret_cast<const float4*>(pr1 + kb + KC);
            pd0 = *reinterpret_cast<const float4*>(pi1 + kb + KC);
            pxv = *reinterpret_cast<const float4*>(xsrc + (size_t)(kb + KC) * C_);
        }
        WG_BAR(bar_id);

        const char* Aw = sA[wg][stage];
        const char* Xw = sX[wg][stage];
#pragma unroll
        for (int kk = 0; kk < KC; kk++) {
            const char* Ab = Aw + kk * 1024;
            const int asw = ((ty + kk) & 15) * 16;
            unsigned long long a[8];
#pragma unroll
            for (int i = 0; i < 4; i++) {
                ulonglong2 t = *reinterpret_cast<const ulonglong2*>(Ab + i * 256 + asw);
                a[2 * i] = t.x; a[2 * i + 1] = t.y;
            }
            const char* Xb = Xw + kk * 256;
            const int xsw = ((tx + kk) & 7) * 16;
            float4 x0 = *reinterpret_cast<const float4*>(Xb + xsw);
            float4 x1 = *reinterpret_cast<const float4*>(Xb + 128 + xsw);
            unsigned long long xv[8];
            xv[0] = pack2(x0.x, x0.x); xv[1] = pack2(x0.y, x0.y);
            xv[2] = pack2(x0.z, x0.z); xv[3] = pack2(x0.w, x0.w);
            xv[4] = pack2(x1.x, x1.x); xv[5] = pack2(x1.y, x1.y);
            xv[6] = pack2(x1.z, x1.z); xv[7] = pack2(x1.w, x1.w);
#pragma unroll
            for (int fi = 0; fi < 8; fi++)
#pragma unroll
                for (int ci = 0; ci < 8; ci++)
                    fma2(acc[fi][ci], a[fi], xv[ci]);
        }
        stage ^= 1;
    }

    // merge wg1 -> wg0 through smem (reuse sA: 32 KB = 32*128*8)
    unsigned long long* scr = reinterpret_cast<unsigned long long*>(&sA[0][0][0]);
#pragma unroll
    for (int ch = 0; ch < 2; ch++) {
        __syncthreads();
        if (wg == 1) {
#pragma unroll
            for (int j = 0; j < 32; j++) {
                int m = ch * 32 + j;
                scr[j * 128 + wtid] = acc[m >> 3][m & 7];
            }
        }
        __syncthreads();
        if (wg == 0) {
#pragma unroll
            for (int j = 0; j < 32; j++) {
                int m = ch * 32 + j;
                add2(acc[m >> 3][m & 7], scr[j * 128 + wtid]);
            }
        }
    }

    if (wg == 0) {
        const int f0 = ftile * 128 + ty * 8;
#pragma unroll
        for (int ci = 0; ci < 8; ci++) {
            int c = tx * 8 + ci;
            ulonglong2* dst = reinterpret_cast<ulonglong2*>(&g_Xft[((size_t)(b * C_ + c)) * F1 + f0]);
#pragma unroll
            for (int i = 0; i < 4; i++) {
                ulonglong2 t;
                t.x = acc[2 * i][ci];
                t.y = acc[2 * i + 1][ci];
                dst[i] = t;
            }
        }
    }
}

// ============================================================================
// Kernel 3: channel mixing + phi modulation + Hermitian expansion.
// g_xf stored [b][f][c].
// ============================================================================
__global__ __launch_bounds__(512) void k_mix(
    const float* __restrict__ w1re, const float* __restrict__ w1im,
    const float* __restrict__ w2re, const float* __restrict__ w2im)
{
    __shared__ float2 Xs[4][64][16];

    const int bid = blockIdx.x;
    const int xm  = bid >> 2;
    const int yh  = (bid >> 1) & 1;
    const int bh  = bid & 1;
    const int tid = threadIdx.x;

    {
        int row  = tid >> 1;
        int half = tid & 1;
        int br = row >> 6, ii = row & 63;
        const float2* src = g_Xft + ((size_t)((bh * 4 + br) * C_ + ii)) * F1
                            + xm * 32 + yh * 16 + half * 8;
#pragma unroll
        for (int j = 0; j < 4; j++) {
            float4 v = reinterpret_cast<const float4*>(src)[j];
            Xs[br][ii][half * 8 + j * 2]     = make_float2(v.x, v.y);
            Xs[br][ii][half * 8 + j * 2 + 1] = make_float2(v.z, v.w);
        }
    }
    __syncthreads();

    const int o   = tid >> 3;
    const int yq  = tid & 7;
    const int y   = yh * 16 + yq * 2;
    const int x32 = xm & 31;
    const float* wre = (xm < 32) ? w1re : w2re;
    const float* wim = (xm < 32) ? w1im : w2im;

    unsigned long long acc0[4] = {0ull, 0ull, 0ull, 0ull};
    unsigned long long acc1[4] = {0ull, 0ull, 0ull, 0ull};

#pragma unroll 4
    for (int ii = 0; ii < 64; ii++) {
        size_t wrow = (size_t)(ii * 64 + o) * 1024 + x32 * 32 + y;
        float2 wr = *reinterpret_cast<const float2*>(wre + wrow);
        float2 wi = *reinterpret_cast<const float2*>(wim + wrow);
        unsigned long long w0a = pack2(wr.x, wi.x);
        unsigned long long w0b = pack2(-wi.x, wr.x);
        unsigned long long w1a = pack2(wr.y, wi.y);
        unsigned long long w1b = pack2(-wi.y, wr.y);
#pragma unroll
        for (int br = 0; br < 4; br++) {
            float2 xv0 = Xs[br][ii][yq * 2];
            float2 xv1 = Xs[br][ii][yq * 2 + 1];
            fma2(acc0[br], pack2(xv0.x, xv0.x), w0a);
            fma2(acc0[br], pack2(xv0.y, xv0.y), w0b);
            fma2(acc1[br], pack2(xv1.x, xv1.x), w1a);
            fma2(acc1[br], pack2(xv1.y, xv1.y), w1b);
        }
    }

    const int sel = (xm < 32) ? 0 : 1;
#pragma unroll
    for (int br = 0; br < 4; br++) {
        int bb = bh * 4 + br;
#pragma unroll
        for (int pp = 0; pp < 2; pp++) {
            int yy = y + pp;
            float2 s = unpack2(pp ? acc1[br] : acc0[br]);
            float2 p = g_phi[sel * (B_ * 1024) + bb * 1024 + x32 * 32 + yy];
            float vr = p.x * s.x - p.y * s.y;
            float vi = p.x * s.y + p.y * s.x;
            int fm = xm * 32 + yy;
            g_xf[((size_t)bb * MFRQ + fm) * C_ + o] = make_float2(vr, -vi);
            if (fm >= 64)
                g_xf[((size_t)bb * MFRQ + (4095 - fm)) * C_ + (63 - o)] = make_float2(vr, vi);
        }
    }
}

// ============================================================================
// Kernel 4: inverse NUFT (real part), K=4032, split-K, 2-stage pipelined.
// X chunk(i,k): float2 pair c=tx*8+2i at k*512 + i*128 + ((tx+k)&7)*16.
// ============================================================================
__global__ __launch_bounds__(256, 1) void k_inverse(
    const float* __restrict__ vire,
    const float* __restrict__ viim,
    float* __restrict__ out)
{
    __shared__ __align__(16) char sA[2][2][KC * 1024];  // 32 KB
    __shared__ __align__(16) char sX[2][2][KC * 512];   // 16 KB  (total 48 KB)

    const int b     = blockIdx.y;
    const int ntile = blockIdx.x;
    const int tid   = threadIdx.x;
    const int wg    = tid >> 7;
    const int wtid  = tid & 127;
    const int tx    = wtid & 7;
    const int ty    = wtid >> 3;

    unsigned long long acc[8][8];
#pragma unroll
    for (int i = 0; i < 8; i++)
#pragma unroll
        for (int j = 0; j < 8; j++) acc[i][j] = 0ull;

    const int KHALF = MFRQ / 2;          // 2016
    const int kbase = wg * KHALF;

    // A fill role
    const int fp = wtid >> 1;
    const int kh = (wtid & 1) * 4;
    const int row0 = ntile * 128 + 2 * fp;
    const float* pr0 = vire + (size_t)row0 * MFRQ + kbase + kh;
    const float* pi0 = viim + (size_t)row0 * MFRQ + kbase + kh;
    const float* pr1 = pr0 + MFRQ;
    const float* pi1 = pi0 + MFRQ;
    const int aoff = (fp & 3) * 256;
    const int ftyp = fp >> 2;

    // X fill role: k-row kx (0..7), sub -> (qx, j pair)
    const int kx  = wtid >> 4;
    const int sub = wtid & 15;
    const int qxf = sub & 7;
    const int jh  = (sub >> 3) * 2;      // j = jh, jh+1
    const float2* xsrc = g_xf + ((size_t)(b * MFRQ) + kbase + kx) * C_ + qxf * 8;
    const int xrot = ((qxf + kx) & 7) * 16;

    const int bar_id = wg + 1;

    // prefetch kb = 0
    float4 pa0 = *reinterpret_cast<const float4*>(pr0);
    float4 pb0 = *reinterpret_cast<const float4*>(pi0);
    float4 pc0 = *reinterpret_cast<const float4*>(pr1);
    float4 pd0 = *reinterpret_cast<const float4*>(pi1);
    float4 px0 = *reinterpret_cast<const float4*>(xsrc + 2 * jh);
    float4 px1 = *reinterpret_cast<const float4*>(xsrc + 2 * jh + 2);

    int stage = 0;
    for (int kb = 0; kb < KHALF; kb += KC) {
        // ---- store prefetched regs into smem[stage] ----
        {
            char* Abase = sA[wg][stage] + aoff;
            float r[4] = {pa0.x, pa0.y, pa0.z, pa0.w};
            float q[4] = {pb0.x, pb0.y, pb0.z, pb0.w};
            float s[4] = {pc0.x, pc0.y, pc0.z, pc0.w};
            float u[4] = {pd0.x, pd0.y, pd0.z, pd0.w};
#pragma unroll
            for (int j = 0; j < 4; j++) {
                int kk = kh + j;
                *reinterpret_cast<float4*>(Abase + kk * 1024 + ((ftyp + kk) & 15) * 16)
                    = make_float4(r[j], q[j], s[j], u[j]);
            }
            char* Xrow = sX[wg][stage] + kx * 512;
            *reinterpret_cast<float4*>(Xrow + jh * 128 + xrot)       = px0;
            *reinterpret_cast<float4*>(Xrow + (jh + 1) * 128 + xrot) = px1;
        }
        // ---- prefetch next block ----
        if (kb + KC < KHALF) {
            pa0 = *reinterpret_cast<const float4*>(pr0 + kb + KC);
            pb0 = *reinterpret_cast<const float4*>(pi0 + kb + KC);
            pc0 = *reinterpret_cast<const float4*>(pr1 + kb + KC);
            pd0 = *reinterpret_cast<const float4*>(pi1 + kb + KC);
            px0 = *reinterpret_cast<const float4*>(xsrc + (size_t)(kb + KC) * C_ + 2 * jh);
            px1 = *reinterpret_cast<const float4*>(xsrc + (size_t)(kb + KC) * C_ + 2 * jh + 2);
        }
        WG_BAR(bar_id);

        const char* Aw = sA[wg][stage];
        const char* Xw = sX[wg][stage];
#pragma unroll
        for (int kk = 0; kk < KC; kk++) {
            const char* Ab = Aw + kk * 1024;
            const int asw = ((ty + kk) & 15) * 16;
            unsigned long long a[8];
#pragma unroll
            for (int i = 0; i < 4; i++) {
                ulonglong2 t = *reinterpret_cast<const ulonglong2*>(Ab + i * 256 + asw);
                a[2 * i] = t.x; a[2 * i + 1] = t.y;
            }
            const char* Xb = Xw + kk * 512;
            const int xsw = ((tx + kk) & 7) * 16;
            unsigned long long xv[8];
#pragma unroll
            for (int i = 0; i < 4; i++) {
                ulonglong2 t = *reinterpret_cast<const ulonglong2*>(Xb + i * 128 + xsw);
                xv[2 * i] = t.x; xv[2 * i + 1] = t.y;
            }
#pragma unroll
            for (int fi = 0; fi < 8; fi++)
#pragma unroll
                for (int ci = 0; ci < 8; ci++)
                    fma2(acc[fi][ci], a[fi], xv[ci]);
        }
        stage ^= 1;
    }

    // merge wg1 -> wg0
    unsigned long long* scr = reinterpret_cast<unsigned long long*>(&sA[0][0][0]);
#pragma unroll
    for (int ch = 0; ch < 2; ch++) {
        __syncthreads();
        if (wg == 1) {
#pragma unroll
            for (int j = 0; j < 32; j++) {
                int m = ch * 32 + j;
                scr[j * 128 + wtid] = acc[m >> 3][m & 7];
            }
        }
        __syncthreads();
        if (wg == 0) {
#pragma unroll
            for (int j = 0; j < 32; j++) {
                int m = ch * 32 + j;
                add2(acc[m >> 3][m & 7], scr[j * 128 + wtid]);
            }
        }
    }

    if (wg == 0) {
        const float sc = 2.0f / (float)NPTS;
        const int n0 = ntile * 128 + ty * 8;
#pragma unroll
        for (int ci = 0; ci < 8; ci++) {
            int c = tx * 8 + ci;
            float r[8];
#pragma unroll
            for (int fi = 0; fi < 8; fi++) {
                float2 s = unpack2(acc[fi][ci]);
                r[fi] = (s.x + s.y) * sc;
            }
            float4* dst = reinterpret_cast<float4*>(out + ((size_t)(b * C_ + c)) * NPTS + n0);
            dst[0] = make_float4(r[0], r[1], r[2], r[3]);
            dst[1] = make_float4(r[4], r[5], r[6], r[7]);
        }
    }
}

// ============================================================================
extern "C" void kernel_launch(void* const* d_in, const int* in_sizes, int n_in,
                              void* d_out, int out_size)
{
    const float* x     = (const float*)d_in[0];
    const float* emb   = (const float*)d_in[1];
    const float* vf_re = (const float*)d_in[2];
    const float* vf_im = (const float*)d_in[3];
    const float* vi_re = (const float*)d_in[4];
    const float* vi_im = (const float*)d_in[5];
    const float* w1_re = (const float*)d_in[6];
    const float* w1_im = (const float*)d_in[7];
    const float* w2_re = (const float*)d_in[8];
    const float* w2_im = (const float*)d_in[9];
    const float* m1_re = (const float*)d_in[10];
    const float* m1_im = (const float*)d_in[11];
    const float* m2_re = (const float*)d_in[12];
    const float* m2_im = (const float*)d_in[13];
    float* out = (float*)d_out;

    k_phi<<<2048, 256>>>(emb, m1_re, m1_im, m2_re, m2_im);
    k_transpose<<<dim3(32, 8), 256>>>(x);
    k_forward<<<dim3(16, 8), 256>>>(vf_re, vf_im);
    k_mix<<<256, 512>>>(w1_re, w1_im, w2_re, w2_im);
    k_inverse<<<dim3(16, 8), 256>>>(vi_re, vi_im, out);
}